// round 9
// baseline (speedup 1.0000x reference)
#include <cuda_runtime.h>
#include <math.h>
#include <stdint.h>

#define TT 1024
#define HH 512

// ---- persistent state (device globals; no allocation allowed) ----
__device__ float g_h[2][16][4][512];  // [parity][group][batch][k] h exchange
__device__ int   g_flag[16][8];       // [group][producer CTA] step flags

// ---------------- packed f32x2 helpers ----------------
__device__ __forceinline__ unsigned long long pack2(float x, float y) {
    unsigned long long r;
    asm("mov.b64 %0, {%1, %2};" : "=l"(r) : "f"(x), "f"(y));
    return r;
}
__device__ __forceinline__ unsigned long long fma2(unsigned long long a,
                                                   unsigned long long b,
                                                   unsigned long long c) {
    unsigned long long d;
    asm("fma.rn.f32x2 %0, %1, %2, %3;" : "=l"(d) : "l"(a), "l"(b), "l"(c));
    return d;
}
__device__ __forceinline__ float2 unpack2(unsigned long long v) {
    float2 r;
    asm("mov.b64 {%0, %1}, %2;" : "=f"(r.x), "=f"(r.y) : "l"(v));
    return r;
}
// broadcast L2 load of two u64 h-pairs ({h_k,h_k+1},{h_k+2,h_k+3})
__device__ __forceinline__ void ldcg_u64x2(const float* p,
                                           unsigned long long& a,
                                           unsigned long long& b) {
    asm volatile("ld.global.cg.v2.u64 {%0, %1}, [%2];"
                 : "=l"(a), "=l"(b) : "l"(p));
}

// ===================== Phase 1: xw = x @ W[0:512] + b  -> out =====================
__global__ void __launch_bounds__(256) gemm_xw_kernel(
    const float* __restrict__ x, const float* __restrict__ Wg,
    const float* __restrict__ bias, float* __restrict__ C)
{
    // block (0,0): reset phase-2 flags and zero the parity-0 h buffer (h_{-1}=0)
    if (blockIdx.x == 0 && blockIdx.y == 0) {
        if (threadIdx.x < 128) ((int*)g_flag)[threadIdx.x] = 0;
        float4* hz = (float4*)g_h[0];
        for (int i = threadIdx.x; i < 16 * 4 * 512 / 4; i += 256)
            hz[i] = make_float4(0.f, 0.f, 0.f, 0.f);
    }

    __shared__ float As[16][132];
    __shared__ float Bs[16][68];

    const int tid = threadIdx.x;
    const int tn  = tid & 15;
    const int tm  = tid >> 4;
    const int m0  = blockIdx.x * 128;
    const int n0  = blockIdx.y * 64;

    unsigned long long acc[8][2];
#pragma unroll
    for (int i = 0; i < 8; i++) { acc[i][0] = 0ull; acc[i][1] = 0ull; }

    for (int k0 = 0; k0 < 512; k0 += 16) {
#pragma unroll
        for (int i = tid; i < 512; i += 256) {
            int m = i >> 2, kq = i & 3;
            float4 v = *(const float4*)(x + (size_t)(m0 + m) * 512 + k0 + kq * 4);
            As[kq * 4 + 0][m] = v.x;
            As[kq * 4 + 1][m] = v.y;
            As[kq * 4 + 2][m] = v.z;
            As[kq * 4 + 3][m] = v.w;
        }
        {
            int kk = tid >> 4, nq = tid & 15;
            float4 v = *(const float4*)(Wg + (size_t)(k0 + kk) * 512 + n0 + nq * 4);
            *(float4*)&Bs[kk][nq * 4] = v;
        }
        __syncthreads();
#pragma unroll
        for (int kk = 0; kk < 16; kk++) {
            ulonglong2 bb = *(const ulonglong2*)&Bs[kk][tn * 4];
#pragma unroll
            for (int i = 0; i < 8; i++) {
                float a = As[kk][tm * 8 + i];
                unsigned long long ap = pack2(a, a);
                acc[i][0] = fma2(ap, bb.x, acc[i][0]);
                acc[i][1] = fma2(ap, bb.y, acc[i][1]);
            }
        }
        __syncthreads();
    }

    float b0 = bias[n0 + tn * 4 + 0];
    float b1 = bias[n0 + tn * 4 + 1];
    float b2 = bias[n0 + tn * 4 + 2];
    float b3 = bias[n0 + tn * 4 + 3];
#pragma unroll
    for (int i = 0; i < 8; i++) {
        int m = m0 + tm * 8 + i;
        float2 p0 = unpack2(acc[i][0]);
        float2 p1 = unpack2(acc[i][1]);
        float4 o;
        o.x = p0.x + b0; o.y = p0.y + b1; o.z = p1.x + b2; o.w = p1.y + b3;
        *(float4*)(C + (size_t)m * 512 + n0 + tn * 4) = o;
    }
}

// ===================== Phase 2: sequential recurrence ==============================
// 16 groups x 8 CTAs (128 persistent), 256 threads. Group g: batches 4g..4g+3.
// CTA c: output cols 64c..64c+63. Warp kc consumes K-chunk kc ONLY:
//   kc == c  -> own chunk from SMEM (this CTA produced it last step)
//   kc != c  -> acquire-poll producer kc's flag, then stream h from L2 (broadcast ldcg)
// No staged reload, no third barrier. Wh in registers as k-pairs (64 u64/thread).
__global__ void __launch_bounds__(256, 1) recurrent_kernel(
    const float* __restrict__ Wg, float* __restrict__ out)
{
    __shared__ __align__(16) float hsown[4][64];  // own chunk h (next step)
    __shared__ float red[8][258];                 // per-chunk partials

    const int tid = threadIdx.x;
    const int g   = blockIdx.x >> 3;   // group 0..15
    const int c   = blockIdx.x & 7;    // col-slice / rank 0..7
    const int kc  = tid >> 5;          // warp id == K-chunk 0..7
    const int jg  = tid & 31;          // cols 2jg, 2jg+1 within slice
    const int bo  = tid >> 6;          // epilogue batch 0..3
    const int col = tid & 63;          // epilogue column within slice

    // ---- Wh slice into registers as k-pairs:
    //      w[k2][cc] = {Wh[kc*64+2k2][c*64+2jg+cc], Wh[kc*64+2k2+1][...]}
    unsigned long long w[32][2];
    {
        const float* wb = Wg + (size_t)(512 + kc * 64) * 512 + c * 64 + jg * 2;
#pragma unroll
        for (int k2 = 0; k2 < 32; k2++) {
            float lo0 = wb[(size_t)(2 * k2) * 512 + 0];
            float hi0 = wb[(size_t)(2 * k2 + 1) * 512 + 0];
            float lo1 = wb[(size_t)(2 * k2) * 512 + 1];
            float hi1 = wb[(size_t)(2 * k2 + 1) * 512 + 1];
            w[k2][0] = pack2(lo0, hi0);
            w[k2][1] = pack2(lo1, hi1);
        }
    }
    ((float*)hsown)[tid] = 0.0f;   // own-chunk h_{-1} = 0
    __syncthreads();

    float* outrow = out + (size_t)(g * 4 + bo) * TT * HH + c * 64 + col;
    int* myflag   = &g_flag[g][c];
    int* theflag  = &g_flag[g][kc];

    for (int t = 0; t < TT; t++) {
        float xwv = outrow[(size_t)t * HH];   // epilogue operand; overlaps the wait

        // 8 accumulators: [batch][colpair-half], each {even-k sum, odd-k sum}
        unsigned long long a00 = 0, a01 = 0, a10 = 0, a11 = 0;
        unsigned long long a20 = 0, a21 = 0, a30 = 0, a31 = 0;

        if (kc == c) {
            // own chunk: SMEM broadcast reads
#pragma unroll
            for (int i4 = 0; i4 < 16; i4++) {
                ulonglong2 q0 = *(const ulonglong2*)&hsown[0][i4 * 4];
                ulonglong2 q1 = *(const ulonglong2*)&hsown[1][i4 * 4];
                ulonglong2 q2 = *(const ulonglong2*)&hsown[2][i4 * 4];
                ulonglong2 q3 = *(const ulonglong2*)&hsown[3][i4 * 4];
                unsigned long long w0 = w[2 * i4][0],     w1 = w[2 * i4][1];
                unsigned long long v0 = w[2 * i4 + 1][0], v1 = w[2 * i4 + 1][1];
                a00 = fma2(q0.x, w0, a00); a01 = fma2(q0.x, w1, a01);
                a10 = fma2(q1.x, w0, a10); a11 = fma2(q1.x, w1, a11);
                a20 = fma2(q2.x, w0, a20); a21 = fma2(q2.x, w1, a21);
                a30 = fma2(q3.x, w0, a30); a31 = fma2(q3.x, w1, a31);
                a00 = fma2(q0.y, v0, a00); a01 = fma2(q0.y, v1, a01);
                a10 = fma2(q1.y, v0, a10); a11 = fma2(q1.y, v1, a11);
                a20 = fma2(q2.y, v0, a20); a21 = fma2(q2.y, v1, a21);
                a30 = fma2(q3.y, v0, a30); a31 = fma2(q3.y, v1, a31);
            }
        } else {
            // remote chunk: wait for producer kc, then stream from L2
            if (t > 0) {
                int v;
                do {
                    asm volatile("ld.acquire.gpu.global.s32 %0, [%1];"
                                 : "=r"(v) : "l"(theflag) : "memory");
                } while (v < t);
            }
            const int p = t & 1;
            const float* h0 = &g_h[p][g][0][kc * 64];
            const float* h1 = &g_h[p][g][1][kc * 64];
            const float* h2 = &g_h[p][g][2][kc * 64];
            const float* h3 = &g_h[p][g][3][kc * 64];
#pragma unroll
            for (int i4 = 0; i4 < 16; i4++) {
                unsigned long long q0x, q0y, q1x, q1y, q2x, q2y, q3x, q3y;
                ldcg_u64x2(h0 + i4 * 4, q0x, q0y);
                ldcg_u64x2(h1 + i4 * 4, q1x, q1y);
                ldcg_u64x2(h2 + i4 * 4, q2x, q2y);
                ldcg_u64x2(h3 + i4 * 4, q3x, q3y);
                unsigned long long w0 = w[2 * i4][0],     w1 = w[2 * i4][1];
                unsigned long long v0 = w[2 * i4 + 1][0], v1 = w[2 * i4 + 1][1];
                a00 = fma2(q0x, w0, a00); a01 = fma2(q0x, w1, a01);
                a10 = fma2(q1x, w0, a10); a11 = fma2(q1x, w1, a11);
                a20 = fma2(q2x, w0, a20); a21 = fma2(q2x, w1, a21);
                a30 = fma2(q3x, w0, a30); a31 = fma2(q3x, w1, a31);
                a00 = fma2(q0y, v0, a00); a01 = fma2(q0y, v1, a01);
                a10 = fma2(q1y, v0, a10); a11 = fma2(q1y, v1, a11);
                a20 = fma2(q2y, v0, a20); a21 = fma2(q2y, v1, a21);
                a30 = fma2(q3y, v0, a30); a31 = fma2(q3y, v1, a31);
            }
        }

        // horizontal even+odd, stash per-chunk partials {col 2jg, col 2jg+1}
        {
            float2 e0 = unpack2(a00), o0 = unpack2(a01);
            float2 e1 = unpack2(a10), o1 = unpack2(a11);
            float2 e2 = unpack2(a20), o2 = unpack2(a21);
            float2 e3 = unpack2(a30), o3 = unpack2(a31);
            *(float2*)&red[kc][0 * 64 + jg * 2] = make_float2(e0.x + e0.y, o0.x + o0.y);
            *(float2*)&red[kc][1 * 64 + jg * 2] = make_float2(e1.x + e1.y, o1.x + o1.y);
            *(float2*)&red[kc][2 * 64 + jg * 2] = make_float2(e2.x + e2.y, o2.x + o2.y);
            *(float2*)&red[kc][3 * 64 + jg * 2] = make_float2(e3.x + e3.y, o3.x + o3.y);
        }
        __syncthreads();

        // epilogue: one (batch, col) per thread  (tid == bo*64+col)
        float z = xwv;
#pragma unroll
        for (int k2 = 0; k2 < 8; k2++) z += red[k2][tid];
        float hv = tanhf(z);
        outrow[(size_t)t * HH] = hv;                 // this IS the output

        if (t + 1 < TT) {
            __stcg(&g_h[(t + 1) & 1][g][bo][c * 64 + col], hv);  // publish to peers
            hsown[bo][col] = hv;                     // own chunk for next step
            __syncthreads();                         // stores issued; red reusable
            if (tid == 0)
                asm volatile("st.release.gpu.global.s32 [%0], %1;"
                             :: "l"(myflag), "r"(t + 1) : "memory");
        }
    }
}

// ======================================================================================
extern "C" void kernel_launch(void* const* d_in, const int* in_sizes, int n_in,
                              void* d_out, int out_size) {
    (void)in_sizes; (void)n_in; (void)out_size;
    const float* x  = (const float*)d_in[0];   // [64,1024,512]
    const float* Wg = (const float*)d_in[1];   // [1024,512]
    const float* bb = (const float*)d_in[2];   // [512]
    float* out = (float*)d_out;                // [64,1024,512]

    gemm_xw_kernel<<<dim3(512, 8), 256>>>(x, Wg, bb, out);
    recurrent_kernel<<<128, 256>>>(Wg, out);
}

// round 10
// speedup vs baseline: 2.3584x; 2.3584x over previous
#include <cuda_runtime.h>
#include <cuda_bf16.h>
#include <math.h>
#include <stdint.h>

#define TT 1024
#define HH 512

// ---- persistent state (device globals; no allocation allowed) ----
__device__ float g_h[2][64 * 512];   // double-buffered h exchange [parity][batch][k]
__device__ int   g_bar[16];          // per-group arrival counters
__device__ __nv_bfloat16 g_xhi[64u * 1024u * 512u];  // 64MB  bf16 split of x
__device__ __nv_bfloat16 g_xlo[64u * 1024u * 512u];  // 64MB
__device__ __nv_bfloat16 g_whi[512 * 512];           // bf16 split of Wx
__device__ __nv_bfloat16 g_wlo[512 * 512];

// ---------------- packed f32x2 helpers (phase-2 compute, verbatim R2) -------------
__device__ __forceinline__ unsigned long long pack2(float x, float y) {
    unsigned long long r;
    asm("mov.b64 %0, {%1, %2};" : "=l"(r) : "f"(x), "f"(y));
    return r;
}
__device__ __forceinline__ unsigned long long fma2(unsigned long long a,
                                                   unsigned long long b,
                                                   unsigned long long c) {
    unsigned long long d;
    asm("fma.rn.f32x2 %0, %1, %2, %3;" : "=l"(d) : "l"(a), "l"(b), "l"(c));
    return d;
}
__device__ __forceinline__ float2 unpack2(unsigned long long v) {
    float2 r;
    asm("mov.b64 {%0, %1}, %2;" : "=f"(r.x), "=f"(r.y) : "l"(v));
    return r;
}

// ---------------- tensor helpers ----------------
__device__ __forceinline__ uint32_t smem_u32(const void* p) {
    uint32_t a;
    asm("{ .reg .u64 t; cvta.to.shared.u64 t, %1; cvt.u32.u64 %0, t; }"
        : "=r"(a) : "l"(p));
    return a;
}
__device__ __forceinline__ uint32_t sw128(uint32_t byte_off) {
    return byte_off ^ ((byte_off >> 3) & 0x70);
}
__device__ __forceinline__ void ldsm_x4(uint32_t& r0, uint32_t& r1,
                                        uint32_t& r2, uint32_t& r3, uint32_t addr) {
    asm volatile("ldmatrix.sync.aligned.m8n8.x4.shared.b16 {%0,%1,%2,%3}, [%4];"
                 : "=r"(r0), "=r"(r1), "=r"(r2), "=r"(r3) : "r"(addr));
}
__device__ __forceinline__ void ldsm_x4t(uint32_t& r0, uint32_t& r1,
                                         uint32_t& r2, uint32_t& r3, uint32_t addr) {
    asm volatile("ldmatrix.sync.aligned.m8n8.x4.trans.shared.b16 {%0,%1,%2,%3}, [%4];"
                 : "=r"(r0), "=r"(r1), "=r"(r2), "=r"(r3) : "r"(addr));
}
__device__ __forceinline__ void mma_bf16(float* d, const uint32_t* a, const uint32_t* b) {
    asm volatile("mma.sync.aligned.m16n8k16.row.col.f32.bf16.bf16.f32 "
                 "{%0,%1,%2,%3}, {%4,%5,%6,%7}, {%8,%9}, {%0,%1,%2,%3};"
                 : "+f"(d[0]), "+f"(d[1]), "+f"(d[2]), "+f"(d[3])
                 : "r"(a[0]), "r"(a[1]), "r"(a[2]), "r"(a[3]), "r"(b[0]), "r"(b[1]));
}
__device__ __forceinline__ void cpasync16(uint32_t sdst, const void* gsrc) {
    asm volatile("cp.async.cg.shared.global [%0], [%1], 16;" :: "r"(sdst), "l"(gsrc));
}

// ===================== conversion: fp32 -> bf16 hi/lo split ========================
__global__ void __launch_bounds__(256) convert_x_kernel(const float* __restrict__ x) {
    const int N4 = 64 * 1024 * 512 / 4;
    for (int i = blockIdx.x * blockDim.x + threadIdx.x; i < N4;
         i += gridDim.x * blockDim.x) {
        float4 v = ((const float4*)x)[i];
        __nv_bfloat16 h0 = __float2bfloat16(v.x);
        __nv_bfloat16 h1 = __float2bfloat16(v.y);
        __nv_bfloat16 h2 = __float2bfloat16(v.z);
        __nv_bfloat16 h3 = __float2bfloat16(v.w);
        __nv_bfloat16 l0 = __float2bfloat16(v.x - __bfloat162float(h0));
        __nv_bfloat16 l1 = __float2bfloat16(v.y - __bfloat162float(h1));
        __nv_bfloat16 l2 = __float2bfloat16(v.z - __bfloat162float(h2));
        __nv_bfloat16 l3 = __float2bfloat16(v.w - __bfloat162float(h3));
        __nv_bfloat162* dh = (__nv_bfloat162*)(g_xhi + 4 * (size_t)i);
        __nv_bfloat162* dl = (__nv_bfloat162*)(g_xlo + 4 * (size_t)i);
        dh[0] = __halves2bfloat162(h0, h1); dh[1] = __halves2bfloat162(h2, h3);
        dl[0] = __halves2bfloat162(l0, l1); dl[1] = __halves2bfloat162(l2, l3);
    }
}
__global__ void __launch_bounds__(256) convert_w_kernel(const float* __restrict__ Wg) {
    if (blockIdx.x == 0 && threadIdx.x < 16) g_bar[threadIdx.x] = 0;  // phase-2 reset
    const int N4 = 512 * 512 / 4;   // first 512 rows of W = Wx
    for (int i = blockIdx.x * blockDim.x + threadIdx.x; i < N4;
         i += gridDim.x * blockDim.x) {
        float4 v = ((const float4*)Wg)[i];
        __nv_bfloat16 h0 = __float2bfloat16(v.x);
        __nv_bfloat16 h1 = __float2bfloat16(v.y);
        __nv_bfloat16 h2 = __float2bfloat16(v.z);
        __nv_bfloat16 h3 = __float2bfloat16(v.w);
        __nv_bfloat16 l0 = __float2bfloat16(v.x - __bfloat162float(h0));
        __nv_bfloat16 l1 = __float2bfloat16(v.y - __bfloat162float(h1));
        __nv_bfloat16 l2 = __float2bfloat16(v.z - __bfloat162float(h2));
        __nv_bfloat16 l3 = __float2bfloat16(v.w - __bfloat162float(h3));
        __nv_bfloat162* dh = (__nv_bfloat162*)(g_whi + 4 * (size_t)i);
        __nv_bfloat162* dl = (__nv_bfloat162*)(g_wlo + 4 * (size_t)i);
        dh[0] = __halves2bfloat162(h0, h1); dh[1] = __halves2bfloat162(h2, h3);
        dl[0] = __halves2bfloat162(l0, l1); dl[1] = __halves2bfloat162(l2, l3);
    }
}

// ===================== Phase 1: tensor GEMM  out = x@Wx + b ========================
// bf16-split: acc = xhi@whi + xhi@wlo + xlo@whi (fp32 accumulate; exact products).
// BM=128, BN=128, BK=64, 256 thr. Warp tile 64x32 (warps 2m x 4n). SW128 smem +
// ldmatrix(.trans) + m16n8k16 HMMA. cp.async 2-stage double buffer.
#define AHI_B 0
#define ALO_B 16384
#define BH0_B 32768
#define BH1_B 40960
#define BL0_B 49152
#define BL1_B 57344
#define STAGE_B 65536

__global__ void __launch_bounds__(256) gemm_bf16_kernel(
    const float* __restrict__ bias, float* __restrict__ C)
{
    extern __shared__ __align__(1024) char smem[];
    const uint32_t sb = smem_u32(smem);

    const int tid = threadIdx.x;
    const int l   = tid & 31;
    const int wid = tid >> 5;
    const int wm  = wid & 1;        // m offset 64*wm
    const int wn  = wid >> 1;       // n offset 32*wn
    const int half = wn >> 1;       // which 64-col B half
    const int nh   = (wn & 1) * 32; // n offset within half
    const int m0  = blockIdx.x * 128;
    const int n0  = blockIdx.y * 128;

    float acc[4][4][4];
#pragma unroll
    for (int i = 0; i < 4; i++)
#pragma unroll
        for (int j = 0; j < 4; j++)
#pragma unroll
            for (int q = 0; q < 4; q++) acc[i][j][q] = 0.0f;

    // ---- stage loader ----
    auto load_tile = [&](int kt, int stg) {
        const uint32_t s0 = sb + stg * STAGE_B;
        const int k0 = kt * 64;
#pragma unroll
        for (int j = 0; j < 4; j++) {               // A: 1024 chunks each
            int cch = tid + j * 256;
            int row = cch >> 3, cc = cch & 7;
            size_t gm = (size_t)(m0 + row) * 512 + k0 + cc * 8;
            uint32_t so = sw128(row * 128 + cc * 16);
            cpasync16(s0 + AHI_B + so, g_xhi + gm);
            cpasync16(s0 + ALO_B + so, g_xlo + gm);
        }
#pragma unroll
        for (int j = 0; j < 2; j++) {               // B halves: 512 chunks each
            int cch = tid + j * 256;
            int row = cch >> 3, cc = cch & 7;
            size_t gm0 = (size_t)(k0 + row) * 512 + n0 + cc * 8;
            uint32_t so = sw128(row * 128 + cc * 16);
            cpasync16(s0 + BH0_B + so, g_whi + gm0);
            cpasync16(s0 + BH1_B + so, g_whi + gm0 + 64);
            cpasync16(s0 + BL0_B + so, g_wlo + gm0);
            cpasync16(s0 + BL1_B + so, g_wlo + gm0 + 64);
        }
    };

    load_tile(0, 0);
    asm volatile("cp.async.commit_group;");

    for (int kt = 0; kt < 8; kt++) {
        if (kt < 7) {
            load_tile(kt + 1, (kt + 1) & 1);
            asm volatile("cp.async.commit_group;");
            asm volatile("cp.async.wait_group 1;");
        } else {
            asm volatile("cp.async.wait_group 0;");
        }
        __syncthreads();

        const uint32_t s0 = sb + (kt & 1) * STAGE_B;
        const uint32_t bbase = s0 + (half ? BH1_B : BH0_B);
        const uint32_t blbase = s0 + (half ? BL1_B : BL0_B);

#pragma unroll
        for (int kk = 0; kk < 4; kk++) {
            uint32_t ahi[4][4], alo[4][4], bhi[4][2], blo[4][2];
            // A fragments: 4 m16 blocks, hi+lo
            const uint32_t aoff = sw128((wm * 64 + (l & 15)) * 128 +
                                        (kk * 16 + ((l >> 4) << 3)) * 2);
#pragma unroll
            for (int mb = 0; mb < 4; mb++) {
                uint32_t ao = sw128((wm * 64 + mb * 16 + (l & 15)) * 128 +
                                    (kk * 16 + ((l >> 4) << 3)) * 2);
                ldsm_x4(ahi[mb][0], ahi[mb][1], ahi[mb][2], ahi[mb][3], s0 + AHI_B + ao);
                ldsm_x4(alo[mb][0], alo[mb][1], alo[mb][2], alo[mb][3], s0 + ALO_B + ao);
            }
            (void)aoff;
            // B fragments: 4 n8 blocks (2 per x4.trans), hi+lo
#pragma unroll
            for (int nb2 = 0; nb2 < 2; nb2++) {
                uint32_t krow = kk * 16 + (l & 7) + (((l >> 3) & 1) << 3);
                uint32_t ncol = nh + (nb2 << 4) + ((l >> 4) << 3);
                uint32_t bo = sw128(krow * 128 + ncol * 2);
                uint32_t r0, r1, r2, r3;
                ldsm_x4t(r0, r1, r2, r3, bbase + bo);
                bhi[2 * nb2][0] = r0; bhi[2 * nb2][1] = r1;
                bhi[2 * nb2 + 1][0] = r2; bhi[2 * nb2 + 1][1] = r3;
                ldsm_x4t(r0, r1, r2, r3, blbase + bo);
                blo[2 * nb2][0] = r0; blo[2 * nb2][1] = r1;
                blo[2 * nb2 + 1][0] = r2; blo[2 * nb2 + 1][1] = r3;
            }
            // 3-pass split accumulate
#pragma unroll
            for (int mb = 0; mb < 4; mb++)
#pragma unroll
                for (int nb = 0; nb < 4; nb++) {
                    mma_bf16(acc[mb][nb], ahi[mb], bhi[nb]);
                    mma_bf16(acc[mb][nb], ahi[mb], blo[nb]);
                    mma_bf16(acc[mb][nb], alo[mb], bhi[nb]);
                }
        }
        __syncthreads();
    }

    // ---- epilogue: c frag layout m16n8: lane l -> rows l/4, l/4+8; cols 2(l%4)+{0,1}
    const int r  = l >> 2;
    const int cq = (l & 3) * 2;
#pragma unroll
    for (int mb = 0; mb < 4; mb++) {
#pragma unroll
        for (int nb = 0; nb < 4; nb++) {
            int colg = n0 + wn * 32 + nb * 8 + cq;
            float2 bv = *(const float2*)(bias + colg);
            int row0 = m0 + wm * 64 + mb * 16 + r;
            float2 o0 = make_float2(acc[mb][nb][0] + bv.x, acc[mb][nb][1] + bv.y);
            float2 o1 = make_float2(acc[mb][nb][2] + bv.x, acc[mb][nb][3] + bv.y);
            *(float2*)(C + (size_t)row0 * 512 + colg) = o0;
            *(float2*)(C + (size_t)(row0 + 8) * 512 + colg) = o1;
        }
    }
}

// ===================== Phase 2: sequential recurrence (VERBATIM R2 best) ===========
__global__ void __launch_bounds__(256, 1) recurrent_kernel(
    const float* __restrict__ Wg, float* __restrict__ out)
{
    __shared__ float4 hsdup[4 * 256];   // [batch][k/2] : {h_k,h_k,h_{k+1},h_{k+1}}
    __shared__ float  red[8 * 260];     // per-K-chunk partial sums

    const int tid = threadIdx.x;
    const int g   = blockIdx.x >> 3;    // group 0..15
    const int c   = blockIdx.x & 7;     // col-slice 0..7
    const int kc  = tid >> 5;           // K-chunk 0..7 (warp id)
    const int jg  = tid & 31;           // cols 2jg, 2jg+1
    const int bo  = tid >> 6;           // epilogue: batch 0..3
    const int col = tid & 63;           // epilogue: column within slice

    unsigned long long w[64];
#pragma unroll
    for (int k = 0; k < 64; k++) {
        const float* p = Wg + (size_t)(512 + kc * 64 + k) * 512 + c * 64 + jg * 2;
        w[k] = *(const unsigned long long*)p;
    }
    for (int i = tid; i < 1024; i += 256)
        hsdup[i] = make_float4(0.f, 0.f, 0.f, 0.f);
    __syncthreads();

    float* outrow = out + (size_t)(g * 4 + bo) * TT * HH + c * 64 + col;
    const int hoff = (g * 4 + bo) * 512 + c * 64 + col;
    int* barp = &g_bar[g];

    for (int t = 0; t < TT; t++) {
        float xwv = outrow[(size_t)t * HH];

        unsigned long long ae0 = 0, ae1 = 0, ae2 = 0, ae3 = 0;
        unsigned long long ao0 = 0, ao1 = 0, ao2 = 0, ao3 = 0;
        const float4* h0 = &hsdup[0 * 256 + kc * 32];
        const float4* h1 = &hsdup[1 * 256 + kc * 32];
        const float4* h2 = &hsdup[2 * 256 + kc * 32];
        const float4* h3 = &hsdup[3 * 256 + kc * 32];
#pragma unroll
        for (int k2 = 0; k2 < 32; k2++) {
            float4 ha = h0[k2];
            float4 hb = h1[k2];
            float4 hc = h2[k2];
            float4 hd = h3[k2];
            unsigned long long we = w[2 * k2], wo = w[2 * k2 + 1];
            ae0 = fma2(pack2(ha.x, ha.y), we, ae0);
            ao0 = fma2(pack2(ha.z, ha.w), wo, ao0);
            ae1 = fma2(pack2(hb.x, hb.y), we, ae1);
            ao1 = fma2(pack2(hb.z, hb.w), wo, ao1);
            ae2 = fma2(pack2(hc.x, hc.y), we, ae2);
            ao2 = fma2(pack2(hc.z, hc.w), wo, ao2);
            ae3 = fma2(pack2(hd.x, hd.y), we, ae3);
            ao3 = fma2(pack2(hd.z, hd.w), wo, ao3);
        }
        {
            float2 e0 = unpack2(ae0), o0 = unpack2(ao0);
            float2 e1 = unpack2(ae1), o1 = unpack2(ao1);
            float2 e2 = unpack2(ae2), o2 = unpack2(ao2);
            float2 e3 = unpack2(ae3), o3 = unpack2(ao3);
            *(float2*)&red[kc * 260 +   0 + jg * 2] = make_float2(e0.x + o0.x, e0.y + o0.y);
            *(float2*)&red[kc * 260 +  64 + jg * 2] = make_float2(e1.x + o1.x, e1.y + o1.y);
            *(float2*)&red[kc * 260 + 128 + jg * 2] = make_float2(e2.x + o2.x, e2.y + o2.y);
            *(float2*)&red[kc * 260 + 192 + jg * 2] = make_float2(e3.x + o3.x, e3.y + o3.y);
        }
        __syncthreads();

        float z = xwv;
#pragma unroll
        for (int k2 = 0; k2 < 8; k2++) z += red[k2 * 260 + bo * 64 + col];
        float hv = tanhf(z);
        outrow[(size_t)t * HH] = hv;
        __stcg(&g_h[(t + 1) & 1][hoff], hv);
        __syncthreads();

        if (t + 1 < TT) {
            if (tid == 0) {
                asm volatile("red.release.gpu.global.add.s32 [%0], 1;"
                             :: "l"(barp) : "memory");
                int target = 8 * (t + 1), v;
                do {
                    asm volatile("ld.acquire.gpu.global.s32 %0, [%1];"
                                 : "=r"(v) : "l"(barp) : "memory");
                } while (v < target);
            }
            __syncthreads();
            const float4* hb4 = ((const float4*)g_h[(t + 1) & 1]) + (size_t)g * 512;
            float4 v0 = __ldcg(hb4 + tid);
            float4 v1 = __ldcg(hb4 + tid + 256);
            int b0i = tid >> 7, q0 = (tid * 2) & 255;
            int b1i = (tid + 256) >> 7, q1 = ((tid + 256) * 2) & 255;
            hsdup[b0i * 256 + q0 + 0] = make_float4(v0.x, v0.x, v0.y, v0.y);
            hsdup[b0i * 256 + q0 + 1] = make_float4(v0.z, v0.z, v0.w, v0.w);
            hsdup[b1i * 256 + q1 + 0] = make_float4(v1.x, v1.x, v1.y, v1.y);
            hsdup[b1i * 256 + q1 + 1] = make_float4(v1.z, v1.z, v1.w, v1.w);
            __syncthreads();
        }
    }
}

// ======================================================================================
extern "C" void kernel_launch(void* const* d_in, const int* in_sizes, int n_in,
                              void* d_out, int out_size) {
    (void)in_sizes; (void)n_in; (void)out_size;
    const float* x  = (const float*)d_in[0];   // [64,1024,512]
    const float* Wg = (const float*)d_in[1];   // [1024,512]
    const float* bb = (const float*)d_in[2];   // [512]
    float* out = (float*)d_out;                // [64,1024,512]

    static int smem_set = 0;
    if (!smem_set) {
        cudaFuncSetAttribute(gemm_bf16_kernel,
                             cudaFuncAttributeMaxDynamicSharedMemorySize, 2 * STAGE_B);
        smem_set = 1;
    }

    convert_x_kernel<<<2048, 256>>>(x);
    convert_w_kernel<<<64, 256>>>(Wg);
    gemm_bf16_kernel<<<dim3(512, 4), 256, 2 * STAGE_B>>>(bb, out);
    recurrent_kernel<<<128, 256>>>(Wg, out);
}